// round 1
// baseline (speedup 1.0000x reference)
#include <cuda_runtime.h>
#include <cstdint>

#define TOKENS      16384
#define DDIM        2048
#define NEXP        64
#define K1_BLOCKS   256
#define K1_THREADS  64
#define TOK_PER_BLK 64
#define DK          32
#define NCHUNK      (DDIM / DK)      // 64
#define K2_WARPS    8
#define K2_BLOCKS   (TOKENS / K2_WARPS)  // 2048
#define IDX_COUNT   (TOKENS * 2)     // 32768

// Scratch (allocation-free: __device__ globals)
__device__ float g_logits[TOKENS * NEXP];       // 4 MB
__device__ float g_partials[K2_BLOCKS * NEXP];  // 512 KB

__device__ __forceinline__ unsigned long long pack2(float x, float y) {
    return ((unsigned long long)__float_as_uint(y) << 32) |
            (unsigned long long)__float_as_uint(x);
}
__device__ __forceinline__ void ffma2(unsigned long long& d,
                                      unsigned long long a,
                                      unsigned long long b) {
    asm("fma.rn.f32x2 %0, %1, %2, %0;" : "+l"(d) : "l"(a), "l"(b));
}
__device__ __forceinline__ float unpack_sum(unsigned long long v) {
    return __uint_as_float((unsigned)v) + __uint_as_float((unsigned)(v >> 32));
}

// ============================================================================
// K1: logits[T,64] = x[T,2048] @ W[64,2048]^T  (fp32 exact, packed f32x2 FMA)
// 256 blocks x 64 threads; 1 token/thread; 64 packed accumulators/thread.
// ============================================================================
__global__ __launch_bounds__(K1_THREADS)
void k1_gemm(const float* __restrict__ x, const float* __restrict__ W) {
    // Xs2: x chunk transposed to [pair j (16)][token (64)] as packed f32x2
    __shared__ unsigned long long Xs2[16 * TOK_PER_BLK];  // 8 KB
    __shared__ float4 Ws4[NEXP * DK / 4];                 // 8 KB, [e][c4]

    const int tid  = threadIdx.x;
    const int tok0 = blockIdx.x * TOK_PER_BLK;

    unsigned long long acc[NEXP];
#pragma unroll
    for (int e = 0; e < NEXP; e++) acc[e] = 0ull;

    for (int c = 0; c < NCHUNK; c++) {
        const int d0 = c * DK;
        // Cooperative staging: 512 float4 of X tile + 512 float4 of W tile
#pragma unroll
        for (int i = 0; i < 8; i++) {
            int f   = tid + K1_THREADS * i;   // 0..511
            int row = f >> 3;                 // token row / expert row
            int c4  = f & 7;                  // float4 column
            float4 v = *reinterpret_cast<const float4*>(
                x + (size_t)(tok0 + row) * DDIM + d0 + c4 * 4);
            Xs2[(c4 * 2 + 0) * TOK_PER_BLK + row] = pack2(v.x, v.y);
            Xs2[(c4 * 2 + 1) * TOK_PER_BLK + row] = pack2(v.z, v.w);
            float4 w = *reinterpret_cast<const float4*>(
                W + (size_t)row * DDIM + d0 + c4 * 4);
            Ws4[f] = w;   // Ws4[e*8 + c4]
        }
        __syncthreads();

        // x chunk -> regs (16 packed pairs, conflict-free LDS.64)
        unsigned long long x2[16];
#pragma unroll
        for (int j = 0; j < 16; j++) x2[j] = Xs2[j * TOK_PER_BLK + tid];

        const ulonglong2* Wp = reinterpret_cast<const ulonglong2*>(Ws4);
#pragma unroll
        for (int e = 0; e < NEXP; e++) {
#pragma unroll
            for (int k = 0; k < 8; k++) {
                ulonglong2 w = Wp[e * 8 + k];   // warp-uniform broadcast LDS.128
                ffma2(acc[e], x2[2 * k],     w.x);
                ffma2(acc[e], x2[2 * k + 1], w.y);
            }
        }
        __syncthreads();
    }

    // Pair-reduce and write logits row (fp32 exact)
    float* out = g_logits + (size_t)(tok0 + tid) * NEXP;
#pragma unroll
    for (int e = 0; e < NEXP; e += 4) {
        float4 v = make_float4(unpack_sum(acc[e]),     unpack_sum(acc[e + 1]),
                               unpack_sum(acc[e + 2]), unpack_sum(acc[e + 3]));
        *reinterpret_cast<float4*>(out + e) = v;
    }
}

// ============================================================================
// K2: per-token softmax + top-2 + normalized weights; deterministic per-block
// usage partials. One warp per token; 8 tokens per 256-thread block.
// ============================================================================
__global__ __launch_bounds__(256)
void k2_topk(float* __restrict__ out, int out_size) {
    __shared__ float pw[K2_WARPS][NEXP];

    const int warp = threadIdx.x >> 5;
    const int lane = threadIdx.x & 31;
    const int t    = blockIdx.x * K2_WARPS + warp;

    const float2 lv = *reinterpret_cast<const float2*>(
        g_logits + (size_t)t * NEXP + lane * 2);
    const float l0 = lv.x, l1 = lv.y;
    const int   i0 = lane * 2, i1 = lane * 2 + 1;

    // lane-local top-2 (tie -> lower index first, matching jax top_k)
    float v1, v2; int j1, j2;
    if (l0 >= l1) { v1 = l0; j1 = i0; v2 = l1; j2 = i1; }
    else          { v1 = l1; j1 = i1; v2 = l0; j2 = i0; }

    // warp butterfly top-2 merge
#pragma unroll
    for (int off = 16; off >= 1; off >>= 1) {
        float ov1 = __shfl_xor_sync(0xFFFFFFFFu, v1, off);
        int   oj1 = __shfl_xor_sync(0xFFFFFFFFu, j1, off);
        float ov2 = __shfl_xor_sync(0xFFFFFFFFu, v2, off);
        int   oj2 = __shfl_xor_sync(0xFFFFFFFFu, j2, off);
        bool a = (v1 > ov1) || (v1 == ov1 && j1 < oj1);
        float n1, n2; int m1, m2;
        if (a) {
            n1 = v1; m1 = j1;
            bool b = (v2 > ov1) || (v2 == ov1 && j2 < oj1);
            if (b) { n2 = v2;  m2 = j2;  } else { n2 = ov1; m2 = oj1; }
        } else {
            n1 = ov1; m1 = oj1;
            bool b = (ov2 > v1) || (ov2 == v1 && oj2 < j1);
            if (b) { n2 = ov2; m2 = oj2; } else { n2 = v1;  m2 = j1;  }
        }
        v1 = n1; j1 = m1; v2 = n2; j2 = m2;
    }

    // softmax (max = v1 known to all lanes after butterfly)
    const float m  = v1;
    const float e0 = __expf(l0 - m);
    const float e1 = __expf(l1 - m);
    float s = e0 + e1;
#pragma unroll
    for (int off = 16; off >= 1; off >>= 1)
        s += __shfl_xor_sync(0xFFFFFFFFu, s, off);
    const float inv = 1.0f / s;

    // per-warp prob row into smem (deterministic: no atomics)
    pw[warp][i0] = e0 * inv;
    pw[warp][i1] = e1 * inv;

    if (lane == 0) {
        // w1 = p1/(p1+p2) = 1/(1+exp(l2-l1)), w2 = 1 - w1
        const float w1 = 1.0f / (1.0f + __expf(v2 - v1));
        out[t * 2]                 = (float)j1;
        out[t * 2 + 1]             = (float)j2;
        out[IDX_COUNT + t * 2]     = w1;
        out[IDX_COUNT + t * 2 + 1] = 1.0f - w1;
    }
    __syncthreads();

    // block usage partial: fixed-order sum over the 8 warps
    if (threadIdx.x < NEXP) {
        float u = 0.0f;
#pragma unroll
        for (int w = 0; w < K2_WARPS; w++) u += pw[w][threadIdx.x];
        g_partials[blockIdx.x * NEXP + threadIdx.x] = u;
    }
}

// ============================================================================
// K3: aux loss = sum_e (mean_t p[t,e] - 1/E)^2, deterministic reduction.
// ============================================================================
__global__ __launch_bounds__(512)
void k3_aux(float* __restrict__ out, int out_size) {
    __shared__ float red[512];
    const int tid  = threadIdx.x;
    const int e    = tid & 63;
    const int part = tid >> 6;   // 8 partitions over K2_BLOCKS

    float s = 0.0f;
    for (int b = part; b < K2_BLOCKS; b += 8)
        s += g_partials[b * NEXP + e];
    red[tid] = s;
    __syncthreads();

    if (tid < NEXP) {
        float u = 0.0f;
#pragma unroll
        for (int p = 0; p < 8; p++) u += red[p * 64 + tid];
        float d = u * (1.0f / (float)TOKENS) - (1.0f / (float)NEXP);
        red[tid] = d * d;
    }
    __syncthreads();

    if (tid == 0) {
        float a = 0.0f;
#pragma unroll
        for (int i = 0; i < NEXP; i++) a += red[i];
        if (out_size > 2 * IDX_COUNT) out[out_size - 1] = a;
    }
}

// ============================================================================
extern "C" void kernel_launch(void* const* d_in, const int* in_sizes, int n_in,
                              void* d_out, int out_size) {
    const float* x = (const float*)d_in[0];   // [4*4096, 2048]
    const float* W = (const float*)d_in[1];   // [64, 2048]
    float* out = (float*)d_out;

    k1_gemm<<<K1_BLOCKS, K1_THREADS>>>(x, W);
    k2_topk<<<K2_BLOCKS, 256>>>(out, out_size);
    k3_aux<<<1, 512>>>(out, out_size);
}

// round 2
// speedup vs baseline: 1.0012x; 1.0012x over previous
#include <cuda_runtime.h>
#include <cstdint>

#define TOKENS      16384
#define DDIM        2048
#define NEXP        64
#define DK          32
#define NCHUNK      (DDIM / DK)          // 64
#define SPLITK      2
#define CHUNKS_PER  (NCHUNK / SPLITK)    // 32
#define TOK_PER_BLK 64
#define K1_XBLOCKS  (TOKENS / TOK_PER_BLK)  // 256
#define K2_WARPS    8
#define K2_BLOCKS   (TOKENS / K2_WARPS)  // 2048
#define IDX_COUNT   (TOKENS * 2)         // 32768

// Scratch (allocation-free: __device__ globals)
__device__ float g_part[SPLITK * TOKENS * NEXP];  // 8 MB split-K partials
__device__ float g_partials[K2_BLOCKS * NEXP];    // 512 KB usage partials

__device__ __forceinline__ unsigned long long pack2(float x, float y) {
    unsigned long long r;
    asm("mov.b64 %0, {%1, %2};" : "=l"(r) : "f"(x), "f"(y));
    return r;
}
__device__ __forceinline__ void ffma2(unsigned long long& d,
                                      unsigned long long a,
                                      unsigned long long b) {
    asm("fma.rn.f32x2 %0, %1, %2, %0;" : "+l"(d) : "l"(a), "l"(b));
}
__device__ __forceinline__ float unpack_sum(unsigned long long v) {
    return __uint_as_float((unsigned)v) + __uint_as_float((unsigned)(v >> 32));
}

// ============================================================================
// K1: partial logits. Block = 64 threads (2 warps), 64 tokens, all 64 experts.
//   warp0 -> experts [0,32), warp1 -> experts [32,64); each thread 2 tokens
//   (lane, lane+32). W read via warp-uniform LDG.128 (L1/L2-resident, coalescer
//   dedups broadcast -> 1 line). x staged through smem transposed into packed
//   f32x2 pairs. Split-K=2 over D via blockIdx.y.
// ============================================================================
__global__ __launch_bounds__(64)
void k1_gemm(const float* __restrict__ x, const float* __restrict__ W) {
    __shared__ unsigned long long Xs2[16 * TOK_PER_BLK];  // 8 KB

    const int tid   = threadIdx.x;
    const int lane  = tid & 31;
    const int warp  = tid >> 5;
    const int tok0  = blockIdx.x * TOK_PER_BLK;
    const int s     = blockIdx.y;
    const int dbase = s * (DDIM / SPLITK);
    const int eBase = warp * 32;

    unsigned long long accA[32], accB[32];
#pragma unroll
    for (int e = 0; e < 32; e++) { accA[e] = 0ull; accB[e] = 0ull; }

    for (int c = 0; c < CHUNKS_PER; c++) {
        const int d0 = dbase + c * DK;

        // Stage x tile [64 tokens x 32 d] transposed to [pair j][token] pairs
#pragma unroll
        for (int i = 0; i < 8; i++) {
            int f   = tid + 64 * i;       // 0..511
            int row = f >> 3;             // token row
            int c4  = f & 7;              // float4 column
            float4 v = __ldg(reinterpret_cast<const float4*>(
                x + (size_t)(tok0 + row) * DDIM + d0) + c4);
            Xs2[(c4 * 2 + 0) * TOK_PER_BLK + row] = pack2(v.x, v.y);
            Xs2[(c4 * 2 + 1) * TOK_PER_BLK + row] = pack2(v.z, v.w);
        }
        __syncthreads();

        // x chunk -> regs for both tokens (conflict-free LDS.64)
        unsigned long long x2a[16], x2b[16];
#pragma unroll
        for (int j = 0; j < 16; j++) {
            x2a[j] = Xs2[j * TOK_PER_BLK + lane];
            x2b[j] = Xs2[j * TOK_PER_BLK + 32 + lane];
        }
        __syncthreads();   // safe to restage next iter after this

        // W via uniform LDG.128; each load feeds 4 FFMA2
#pragma unroll
        for (int e = 0; e < 32; e++) {
            const float4* wrow = reinterpret_cast<const float4*>(
                W + (size_t)(eBase + e) * DDIM + d0);
#pragma unroll
            for (int k = 0; k < 8; k++) {
                float4 w = __ldg(wrow + k);
                unsigned long long wlo = pack2(w.x, w.y);
                unsigned long long whi = pack2(w.z, w.w);
                ffma2(accA[e], x2a[2 * k],     wlo);
                ffma2(accB[e], x2b[2 * k],     wlo);
                ffma2(accA[e], x2a[2 * k + 1], whi);
                ffma2(accB[e], x2b[2 * k + 1], whi);
            }
        }
    }

    // Store partial logits (pair-reduced)
    float* outA = g_part + ((size_t)s * TOKENS + tok0 + lane) * NEXP + eBase;
    float* outB = g_part + ((size_t)s * TOKENS + tok0 + 32 + lane) * NEXP + eBase;
#pragma unroll
    for (int e = 0; e < 32; e += 4) {
        float4 va = make_float4(unpack_sum(accA[e]),     unpack_sum(accA[e + 1]),
                                unpack_sum(accA[e + 2]), unpack_sum(accA[e + 3]));
        *reinterpret_cast<float4*>(outA + e) = va;
        float4 vb = make_float4(unpack_sum(accB[e]),     unpack_sum(accB[e + 1]),
                                unpack_sum(accB[e + 2]), unpack_sum(accB[e + 3]));
        *reinterpret_cast<float4*>(outB + e) = vb;
    }
}

// ============================================================================
// K2: sum split-K partials, softmax + top-2 + normalized weights; deterministic
// per-block usage partials. One warp per token.
// ============================================================================
__global__ __launch_bounds__(256)
void k2_topk(float* __restrict__ out, int out_size) {
    __shared__ float pw[K2_WARPS][NEXP];

    const int warp = threadIdx.x >> 5;
    const int lane = threadIdx.x & 31;
    const int t    = blockIdx.x * K2_WARPS + warp;

    const float2 pa = *reinterpret_cast<const float2*>(
        g_part + (size_t)t * NEXP + lane * 2);
    const float2 pb = *reinterpret_cast<const float2*>(
        g_part + (size_t)TOKENS * NEXP + (size_t)t * NEXP + lane * 2);
    const float l0 = pa.x + pb.x, l1 = pa.y + pb.y;
    const int   i0 = lane * 2, i1 = lane * 2 + 1;

    // lane-local top-2 (tie -> lower index, matching jax top_k)
    float v1, v2; int j1, j2;
    if (l0 >= l1) { v1 = l0; j1 = i0; v2 = l1; j2 = i1; }
    else          { v1 = l1; j1 = i1; v2 = l0; j2 = i0; }

    // warp butterfly top-2 merge
#pragma unroll
    for (int off = 16; off >= 1; off >>= 1) {
        float ov1 = __shfl_xor_sync(0xFFFFFFFFu, v1, off);
        int   oj1 = __shfl_xor_sync(0xFFFFFFFFu, j1, off);
        float ov2 = __shfl_xor_sync(0xFFFFFFFFu, v2, off);
        int   oj2 = __shfl_xor_sync(0xFFFFFFFFu, j2, off);
        bool a = (v1 > ov1) || (v1 == ov1 && j1 < oj1);
        float n1, n2; int m1, m2;
        if (a) {
            n1 = v1; m1 = j1;
            bool b = (v2 > ov1) || (v2 == ov1 && j2 < oj1);
            if (b) { n2 = v2;  m2 = j2;  } else { n2 = ov1; m2 = oj1; }
        } else {
            n1 = ov1; m1 = oj1;
            bool b = (ov2 > v1) || (ov2 == v1 && oj2 < j1);
            if (b) { n2 = ov2; m2 = oj2; } else { n2 = v1;  m2 = j1;  }
        }
        v1 = n1; j1 = m1; v2 = n2; j2 = m2;
    }

    // softmax (max = v1 known to all lanes)
    const float m  = v1;
    const float e0 = __expf(l0 - m);
    const float e1 = __expf(l1 - m);
    float sum = e0 + e1;
#pragma unroll
    for (int off = 16; off >= 1; off >>= 1)
        sum += __shfl_xor_sync(0xFFFFFFFFu, sum, off);
    const float inv = 1.0f / sum;

    pw[warp][i0] = e0 * inv;
    pw[warp][i1] = e1 * inv;

    if (lane == 0) {
        const float w1 = 1.0f / (1.0f + __expf(v2 - v1));
        out[t * 2]                 = (float)j1;
        out[t * 2 + 1]             = (float)j2;
        out[IDX_COUNT + t * 2]     = w1;
        out[IDX_COUNT + t * 2 + 1] = 1.0f - w1;
    }
    __syncthreads();

    // block usage partial: fixed-order sum over the 8 warps (deterministic)
    if (threadIdx.x < NEXP) {
        float u = 0.0f;
#pragma unroll
        for (int w = 0; w < K2_WARPS; w++) u += pw[w][threadIdx.x];
        g_partials[blockIdx.x * NEXP + threadIdx.x] = u;
    }
}

// ============================================================================
// K3: aux loss = sum_e (mean_t p[t,e] - 1/E)^2, deterministic reduction.
// ============================================================================
__global__ __launch_bounds__(512)
void k3_aux(float* __restrict__ out, int out_size) {
    __shared__ float red[512];
    const int tid  = threadIdx.x;
    const int e    = tid & 63;
    const int part = tid >> 6;   // 8 partitions over K2_BLOCKS

    float s = 0.0f;
    for (int b = part; b < K2_BLOCKS; b += 8)
        s += g_partials[b * NEXP + e];
    red[tid] = s;
    __syncthreads();

    if (tid < NEXP) {
        float u = 0.0f;
#pragma unroll
        for (int p = 0; p < 8; p++) u += red[p * 64 + tid];
        float d = u * (1.0f / (float)TOKENS) - (1.0f / (float)NEXP);
        red[tid] = d * d;
    }
    __syncthreads();

    if (tid == 0) {
        float a = 0.0f;
#pragma unroll
        for (int i = 0; i < NEXP; i++) a += red[i];
        if (out_size > 2 * IDX_COUNT) out[out_size - 1] = a;
    }
}

// ============================================================================
extern "C" void kernel_launch(void* const* d_in, const int* in_sizes, int n_in,
                              void* d_out, int out_size) {
    const float* x = (const float*)d_in[0];   // [16384, 2048]
    const float* W = (const float*)d_in[1];   // [64, 2048]
    float* out = (float*)d_out;

    dim3 g1(K1_XBLOCKS, SPLITK);
    k1_gemm<<<g1, TOK_PER_BLK>>>(x, W);
    k2_topk<<<K2_BLOCKS, 256>>>(out, out_size);
    k3_aux<<<1, 512>>>(out, out_size);
}

// round 6
// speedup vs baseline: 3.8684x; 3.8638x over previous
#include <cuda_runtime.h>
#include <cstdint>

#define TOKENS    16384
#define DDIM      2048
#define NEXP      64
#define MTILE     256
#define SPLITK    2
#define KHALF     (DDIM / SPLITK)        // 1024
#define KC        32
#define NCHUNK    (KHALF / KC)           // 32
#define ROWB      144                    // padded row stride: 36 floats (conflict-free)
#define XBYTES    (MTILE * ROWB)         // 36864
#define WBYTES    (NEXP * ROWB)          // 9216
#define STAGE     (XBYTES + 2 * WBYTES)  // 55296
#define SMEM_BYTES (2 * STAGE)           // 110592
#define IDX_COUNT (TOKENS * 2)
#define K2_WARPS  8
#define K2_BLOCKS (TOKENS / K2_WARPS)    // 2048

// Scratch (allocation-free)
__device__ uint32_t g_Whi[NEXP * DDIM];               // tf32 hi
__device__ uint32_t g_Wlo[NEXP * DDIM];               // tf32 lo
__device__ float    g_part[SPLITK * TOKENS * NEXP];   // 8 MB split-K partial logits
__device__ float    g_partials[K2_BLOCKS * NEXP];     // usage partials

// ---------------- PTX helpers (base sm_103-safe: no tcgen05) ----------------
__device__ __forceinline__ uint32_t smem_u32(const void* p) {
    uint32_t a;
    asm("{ .reg .u64 t; cvta.to.shared.u64 t, %1; cvt.u32.u64 %0, t; }" : "=r"(a) : "l"(p));
    return a;
}
__device__ __forceinline__ uint32_t tf32_rna(float f) {
    uint32_t r; asm("cvt.rna.tf32.f32 %0, %1;" : "=r"(r) : "f"(f)); return r;
}
__device__ __forceinline__ void cpa16(uint32_t dst, const void* src) {
    asm volatile("cp.async.cg.shared.global [%0], [%1], 16;" :: "r"(dst), "l"(src) : "memory");
}
__device__ __forceinline__ void cpa_commit() {
    asm volatile("cp.async.commit_group;" ::: "memory");
}
__device__ __forceinline__ void cpa_wait1() {
    asm volatile("cp.async.wait_group 1;" ::: "memory");
}
__device__ __forceinline__ void ldsm_x4(uint32_t* r, uint32_t addr) {
    asm volatile("ldmatrix.sync.aligned.m8n8.x4.shared.b16 {%0,%1,%2,%3}, [%4];"
                 : "=r"(r[0]), "=r"(r[1]), "=r"(r[2]), "=r"(r[3]) : "r"(addr));
}
__device__ __forceinline__ void mma_tf32(float* d, const uint32_t* a, const uint32_t* b) {
    asm volatile(
        "mma.sync.aligned.m16n8k8.row.col.f32.tf32.tf32.f32 "
        "{%0,%1,%2,%3}, {%4,%5,%6,%7}, {%8,%9}, {%0,%1,%2,%3};"
        : "+f"(d[0]), "+f"(d[1]), "+f"(d[2]), "+f"(d[3])
        : "r"(a[0]), "r"(a[1]), "r"(a[2]), "r"(a[3]), "r"(b[0]), "r"(b[1]));
}

// ============================================================================
// K0: pre-split W into tf32 hi/lo
// ============================================================================
__global__ __launch_bounds__(256)
void k0_split(const float* __restrict__ W) {
    int i = blockIdx.x * 256 + threadIdx.x;
    if (i < NEXP * DDIM) {
        float w = W[i];
        uint32_t h = tf32_rna(w);
        g_Whi[i] = h;
        g_Wlo[i] = tf32_rna(w - __uint_as_float(h));
    }
}

// ============================================================================
// K1: 3xTF32 mma.sync GEMM. 128 blocks (64 M-tiles x split-K 2) x 256 threads.
// Warp w owns tokens [w*32, w*32+32) of its tile, all 64 experts.
// cp.async double-buffered staging: raw x (split to tf32 in regs) + W hi/lo.
// ============================================================================
__global__ __launch_bounds__(256)
void k1_gemm(const float* __restrict__ x) {
    extern __shared__ char dsm[];
    const int tid  = threadIdx.x;
    const int lane = tid & 31;
    const int w    = tid >> 5;
    const int tile = blockIdx.x >> 1;
    const int s    = blockIdx.x & 1;
    const int tok0 = tile * MTILE;
    const int koff = s * KHALF;
    const uint32_t sb = smem_u32(dsm);

    // cp.async source pointers / dest offsets (per chunk: advance src by KC floats)
    const float* xsrc[8]; uint32_t xdst[8];
#pragma unroll
    for (int i = 0; i < 8; i++) {
        int f = tid + 256 * i, row = f >> 3, c4 = f & 7;
        xsrc[i] = x + (size_t)(tok0 + row) * DDIM + koff + c4 * 4;
        xdst[i] = (uint32_t)(row * ROWB + c4 * 16);
    }
    const float* wsrc[4]; uint32_t wdst[4];
#pragma unroll
    for (int i = 0; i < 4; i++) {
        int f = tid + 256 * i, row = (f >> 3) & 63, c4 = f & 7, arr = f >> 9;
        const uint32_t* wb = arr ? g_Wlo : g_Whi;
        wsrc[i] = (const float*)(wb + (size_t)row * DDIM + koff + c4 * 4);
        wdst[i] = (uint32_t)(XBYTES + arr * WBYTES + row * ROWB + c4 * 16);
    }

    // ldmatrix per-lane offsets
    const int rowin = lane & 7;
    const uint32_t aoff = (uint32_t)((rowin + ((lane >> 3) & 1) * 8) * ROWB + ((lane >> 4) & 1) * 16);
    const uint32_t boff = (uint32_t)((rowin + ((lane >> 4) & 1) * 8) * ROWB + ((lane >> 3) & 1) * 16);

    float acc[2][8][4];
#pragma unroll
    for (int g = 0; g < 2; g++)
#pragma unroll
        for (int n = 0; n < 8; n++)
#pragma unroll
            for (int r = 0; r < 4; r++) acc[g][n][r] = 0.0f;

    // Prologue: stage chunks 0 and 1
#pragma unroll
    for (int st = 0; st < 2; st++) {
        const uint32_t B = sb + st * STAGE;
#pragma unroll
        for (int i = 0; i < 8; i++) cpa16(B + xdst[i], xsrc[i] + st * KC);
#pragma unroll
        for (int i = 0; i < 4; i++) cpa16(B + wdst[i], wsrc[i] + st * KC);
        cpa_commit();
    }

    for (int c = 0; c < NCHUNK; c++) {
        cpa_wait1();
        __syncthreads();

        const uint32_t XS = sb + (c & 1) * STAGE;
        const uint32_t WH = XS + XBYTES;
        const uint32_t WL = WH + WBYTES;

#pragma unroll
        for (int ks = 0; ks < 4; ks++) {
            // A fragments: raw x via ldmatrix, tf32 split in regs
            uint32_t Ah[2][4], Al[2][4];
#pragma unroll
            for (int g = 0; g < 2; g++) {
                uint32_t ar[4];
                ldsm_x4(ar, XS + (uint32_t)((w * 32 + g * 16) * ROWB + ks * 32) + aoff);
#pragma unroll
                for (int r = 0; r < 4; r++) {
                    float xf = __uint_as_float(ar[r]);
                    uint32_t h = tf32_rna(xf);
                    Ah[g][r] = h;
                    Al[g][r] = tf32_rna(xf - __uint_as_float(h));
                }
            }
            // B fragments: 4 x4 per split cover 64 experts (b0,b1 per 8-expert group)
            uint32_t Bh[8][2], Bl[8][2];
#pragma unroll
            for (int np = 0; np < 4; np++) {
                uint32_t t[4];
                ldsm_x4(t, WH + (uint32_t)(np * 16 * ROWB + ks * 32) + boff);
                Bh[2 * np][0] = t[0]; Bh[2 * np][1] = t[1];
                Bh[2 * np + 1][0] = t[2]; Bh[2 * np + 1][1] = t[3];
                ldsm_x4(t, WL + (uint32_t)(np * 16 * ROWB + ks * 32) + boff);
                Bl[2 * np][0] = t[0]; Bl[2 * np][1] = t[1];
                Bl[2 * np + 1][0] = t[2]; Bl[2 * np + 1][1] = t[3];
            }
            // 3xTF32: AhBh + AhBl + AlBh
#pragma unroll
            for (int g = 0; g < 2; g++)
#pragma unroll
                for (int n = 0; n < 8; n++) {
                    mma_tf32(acc[g][n], Ah[g], Bh[n]);
                    mma_tf32(acc[g][n], Ah[g], Bl[n]);
                    mma_tf32(acc[g][n], Al[g], Bh[n]);
                }
        }

        __syncthreads();
        // Stage chunk c+2 into the buffer just freed
        if (c + 2 < NCHUNK) {
            const uint32_t B = sb + (c & 1) * STAGE;
            const int o = (c + 2) * KC;
#pragma unroll
            for (int i = 0; i < 8; i++) cpa16(B + xdst[i], xsrc[i] + o);
#pragma unroll
            for (int i = 0; i < 4; i++) cpa16(B + wdst[i], wsrc[i] + o);
        }
        cpa_commit();   // empty group near tail keeps wait_group accounting aligned
    }

    // Store partial logits: c0,c1 -> (row, col..col+1); c2,c3 -> (row+8, ...)
    float* base = g_part + ((size_t)s * TOKENS + tok0 + w * 32) * NEXP;
#pragma unroll
    for (int g = 0; g < 2; g++)
#pragma unroll
        for (int n = 0; n < 8; n++) {
            const int r0  = g * 16 + (lane >> 2);
            const int col = n * 8 + (lane & 3) * 2;
            *reinterpret_cast<float2*>(base + (size_t)r0 * NEXP + col) =
                make_float2(acc[g][n][0], acc[g][n][1]);
            *reinterpret_cast<float2*>(base + (size_t)(r0 + 8) * NEXP + col) =
                make_float2(acc[g][n][2], acc[g][n][3]);
        }
}

// ============================================================================
// K2: sum split-K partials, softmax + top-2 + weights; deterministic usage
// partials. One warp per token. (Verified in round 2.)
// ============================================================================
__global__ __launch_bounds__(256)
void k2_topk(float* __restrict__ out, int out_size) {
    __shared__ float pw[K2_WARPS][NEXP];

    const int warp = threadIdx.x >> 5;
    const int lane = threadIdx.x & 31;
    const int t    = blockIdx.x * K2_WARPS + warp;

    const float2 pa = *reinterpret_cast<const float2*>(
        g_part + (size_t)t * NEXP + lane * 2);
    const float2 pb = *reinterpret_cast<const float2*>(
        g_part + (size_t)TOKENS * NEXP + (size_t)t * NEXP + lane * 2);
    const float l0 = pa.x + pb.x, l1 = pa.y + pb.y;
    const int   i0 = lane * 2, i1 = lane * 2 + 1;

    float v1, v2; int j1, j2;
    if (l0 >= l1) { v1 = l0; j1 = i0; v2 = l1; j2 = i1; }
    else          { v1 = l1; j1 = i1; v2 = l0; j2 = i0; }

#pragma unroll
    for (int off = 16; off >= 1; off >>= 1) {
        float ov1 = __shfl_xor_sync(0xFFFFFFFFu, v1, off);
        int   oj1 = __shfl_xor_sync(0xFFFFFFFFu, j1, off);
        float ov2 = __shfl_xor_sync(0xFFFFFFFFu, v2, off);
        int   oj2 = __shfl_xor_sync(0xFFFFFFFFu, j2, off);
        bool a = (v1 > ov1) || (v1 == ov1 && j1 < oj1);
        float n1, n2; int m1, m2;
        if (a) {
            n1 = v1; m1 = j1;
            bool b = (v2 > ov1) || (v2 == ov1 && j2 < oj1);
            if (b) { n2 = v2;  m2 = j2;  } else { n2 = ov1; m2 = oj1; }
        } else {
            n1 = ov1; m1 = oj1;
            bool b = (ov2 > v1) || (ov2 == v1 && oj2 < j1);
            if (b) { n2 = ov2; m2 = oj2; } else { n2 = v1;  m2 = j1;  }
        }
        v1 = n1; j1 = m1; v2 = n2; j2 = m2;
    }

    const float m  = v1;
    const float e0 = __expf(l0 - m);
    const float e1 = __expf(l1 - m);
    float sum = e0 + e1;
#pragma unroll
    for (int off = 16; off >= 1; off >>= 1)
        sum += __shfl_xor_sync(0xFFFFFFFFu, sum, off);
    const float inv = 1.0f / sum;

    pw[warp][i0] = e0 * inv;
    pw[warp][i1] = e1 * inv;

    if (lane == 0) {
        const float w1 = 1.0f / (1.0f + __expf(v2 - v1));
        out[t * 2]                 = (float)j1;
        out[t * 2 + 1]             = (float)j2;
        out[IDX_COUNT + t * 2]     = w1;
        out[IDX_COUNT + t * 2 + 1] = 1.0f - w1;
    }
    __syncthreads();

    if (threadIdx.x < NEXP) {
        float u = 0.0f;
#pragma unroll
        for (int w = 0; w < K2_WARPS; w++) u += pw[w][threadIdx.x];
        g_partials[blockIdx.x * NEXP + threadIdx.x] = u;
    }
}

// ============================================================================
// K3: aux loss, deterministic reduction.
// ============================================================================
__global__ __launch_bounds__(512)
void k3_aux(float* __restrict__ out, int out_size) {
    __shared__ float red[512];
    const int tid  = threadIdx.x;
    const int e    = tid & 63;
    const int part = tid >> 6;

    float s = 0.0f;
    for (int b = part; b < K2_BLOCKS; b += 8)
        s += g_partials[b * NEXP + e];
    red[tid] = s;
    __syncthreads();

    if (tid < NEXP) {
        float u = 0.0f;
#pragma unroll
        for (int p = 0; p < 8; p++) u += red[p * 64 + tid];
        float d = u * (1.0f / (float)TOKENS) - (1.0f / (float)NEXP);
        red[tid] = d * d;
    }
    __syncthreads();

    if (tid == 0) {
        float a = 0.0f;
#pragma unroll
        for (int i = 0; i < NEXP; i++) a += red[i];
        if (out_size > 2 * IDX_COUNT) out[out_size - 1] = a;
    }
}

// ============================================================================
extern "C" void kernel_launch(void* const* d_in, const int* in_sizes, int n_in,
                              void* d_out, int out_size) {
    const float* x = (const float*)d_in[0];   // [16384, 2048]
    const float* W = (const float*)d_in[1];   // [64, 2048]
    float* out = (float*)d_out;

    cudaFuncSetAttribute(k1_gemm, cudaFuncAttributeMaxDynamicSharedMemorySize, SMEM_BYTES);

    k0_split<<<(NEXP * DDIM + 255) / 256, 256>>>(W);
    k1_gemm<<<(TOKENS / MTILE) * SPLITK, 256, SMEM_BYTES>>>(x);
    k2_topk<<<K2_BLOCKS, 256>>>(out, out_size);
    k3_aux<<<1, 512>>>(out, out_size);
}